// round 4
// baseline (speedup 1.0000x reference)
#include <cuda_runtime.h>

// SNSCell: B=64 batch, S=512 sensory, N=512 state, M=128 motor, 6 unfolds, dt=0.1
#define Bn 64
#define Nn 512
#define Sn 512
#define Mn 128
#define NUNF 6
#define DELTA (0.1f / 6.0f)

#define JT 32          // j (postsynaptic) tile per CTA (lane = j)
#define NJT 16         // Nn / JT
#define NBG 2          // batch groups per step
#define BB 32          // batches per CTA
#define KC 8           // i-reduction splits
#define CI 64          // i chunk per CTA (Nn / KC)
#define TPB 256        // 8 warps; warp -> 4 batches
#define VST 36         // padded smem stride for v chunk rows (floats), %4==0

// ---------------- scratch (static device memory; no allocations) ----------------
__device__ float4 g_P[Nn * Nn];       // fused internal params {1/2s, (s-mu)/2s, mask*erev, mask*w}
__device__ float4 g_SP[Sn * Nn];      // fused sensory params
__device__ float  g_x[Bn * Sn];       // mapped inputs
__device__ float  g_v[2 * Bn * Nn];   // ping-pong state
__device__ float  g_srev[Bn * Nn];    // sensory rev sum (+bias)
__device__ float  g_sw[Bn * Nn];      // sensory w sum
__device__ float2 g_part[KC * Bn * Nn];   // per-split partials {rev, w} (plain stores)
__device__ float2 g_spart[KC * Bn * Nn];  // sensory partials (used in first step only)
__device__ unsigned g_cnt[NJT * NBG];     // arrival counters (kept zeroed)

__device__ __forceinline__ float satfma(float a, float b, float c) {
    float d;
    asm("fma.rn.sat.f32 %0, %1, %2, %3;" : "=f"(d) : "f"(a), "f"(b), "f"(c));
    return d;
}

// ---------------- prep: fuse parameters (vectorized), map inputs, zero counters ----------------
__device__ __forceinline__ float4 fuse1(float sg, float m, float e, float wv, float mk) {
    float a = 1.0f / (2.0f * sg);
    float4 p;
    p.x = a;
    p.y = (sg - m) * a;
    p.z = mk * e;
    p.w = mk * wv;
    return p;
}

__global__ void prep_kernel(const float* __restrict__ sigma, const float* __restrict__ mu,
                            const float* __restrict__ erev,  const float* __restrict__ wmat,
                            const float* __restrict__ mask,
                            const float* __restrict__ ssigma, const float* __restrict__ smu,
                            const float* __restrict__ serev,  const float* __restrict__ swmat,
                            const float* __restrict__ smask,
                            const float* __restrict__ inputs, const float* __restrict__ iw,
                            const float* __restrict__ ib)
{
    int stride = gridDim.x * blockDim.x;
    int tid = blockIdx.x * blockDim.x + threadIdx.x;

    const float4* sg4 = (const float4*)sigma;
    const float4* mu4 = (const float4*)mu;
    const float4* er4 = (const float4*)erev;
    const float4* w4  = (const float4*)wmat;
    const float4* mk4 = (const float4*)mask;
    for (int i = tid; i < Nn * Nn / 4; i += stride) {
        float4 sg = sg4[i], m = mu4[i], e = er4[i], ww = w4[i], mk = mk4[i];
        g_P[4*i+0] = fuse1(sg.x, m.x, e.x, ww.x, mk.x);
        g_P[4*i+1] = fuse1(sg.y, m.y, e.y, ww.y, mk.y);
        g_P[4*i+2] = fuse1(sg.z, m.z, e.z, ww.z, mk.z);
        g_P[4*i+3] = fuse1(sg.w, m.w, e.w, ww.w, mk.w);
    }
    const float4* ssg4 = (const float4*)ssigma;
    const float4* smu4 = (const float4*)smu;
    const float4* ser4 = (const float4*)serev;
    const float4* sw4  = (const float4*)swmat;
    const float4* smk4 = (const float4*)smask;
    for (int i = tid; i < Sn * Nn / 4; i += stride) {
        float4 sg = ssg4[i], m = smu4[i], e = ser4[i], ww = sw4[i], mk = smk4[i];
        g_SP[4*i+0] = fuse1(sg.x, m.x, e.x, ww.x, mk.x);
        g_SP[4*i+1] = fuse1(sg.y, m.y, e.y, ww.y, mk.y);
        g_SP[4*i+2] = fuse1(sg.z, m.z, e.z, ww.z, mk.z);
        g_SP[4*i+3] = fuse1(sg.w, m.w, e.w, ww.w, mk.w);
    }
    const float4* in4 = (const float4*)inputs;
    const float4* iw4 = (const float4*)iw;
    const float4* ib4 = (const float4*)ib;
    float4* x4 = (float4*)g_x;
    for (int i = tid; i < Bn * Sn / 4; i += stride) {
        int s4i = i & (Sn / 4 - 1);
        float4 a = in4[i], wv = iw4[s4i], bv = ib4[s4i];
        float4 o;
        o.x = fmaf(a.x, wv.x, bv.x);
        o.y = fmaf(a.y, wv.y, bv.y);
        o.z = fmaf(a.z, wv.z, bv.z);
        o.w = fmaf(a.w, wv.w, bv.w);
        x4[i] = o;
    }
    if (tid < NJT * NBG) g_cnt[tid] = 0u;
}

// ---------------- fused reduce + combine step kernel ----------------
// CTA = (jt, bg, z). For FIRST, z in [0,16): z<8 -> internal chunk z on vin,
// z>=8 -> sensory chunk (z-8) on g_x into g_spart. Otherwise z in [0,8).
// Each CTA: 64 i x 32 j x 32 b, partials stored as plain float2. The last CTA
// to arrive for (jt,bg) combines all partials and applies the v-update.
template <bool FIRST, bool LAST>
__global__ void __launch_bounds__(TPB, 4) step_kernel(const float* __restrict__ vin,
                                                      float* __restrict__ vout,
                                                      const float* __restrict__ tau,
                                                      const float* __restrict__ bias,
                                                      float* __restrict__ outp,
                                                      const float* __restrict__ ow,
                                                      const float* __restrict__ ob)
{
    __shared__ __align__(16) float  vs[CI * VST];
    __shared__ __align__(16) float4 ps[CI * JT];

    int jt = blockIdx.x, bg = blockIdx.y, z = blockIdx.z;
    bool sensory = FIRST && (z >= KC);
    int kc = sensory ? z - KC : z;
    const float4* __restrict__ P   = sensory ? g_SP : g_P;
    const float*  __restrict__ src = sensory ? g_x  : vin;

    int tid = threadIdx.x;
    int i0  = kc * CI;
    int jc0 = jt * JT;

    // stage v/x chunk transposed: vs[il][b]; lanes sweep il -> coalesced global reads
    for (int t = tid; t < CI * BB; t += TPB) {
        int il = t & (CI - 1);
        int b  = t >> 6;
        vs[il * VST + b] = src[(bg * BB + b) * 512 + i0 + il];
    }
    // stage P tile: ps[row*32 + col]; 512B-contiguous reads per warp
    for (int t = tid; t < CI * JT; t += TPB) {
        int row = t >> 5;
        int col = t & 31;
        ps[t] = __ldg(&P[(size_t)(i0 + row) * Nn + jc0 + col]);
    }
    __syncthreads();

    int lane = tid & 31;
    int warp = tid >> 5;
    int bl0  = warp * 4;          // local batch base (0..28)
    int jg   = jc0 + lane;

    float r[4], wv[4];
#pragma unroll
    for (int k = 0; k < 4; k++) { r[k] = 0.0f; wv[k] = 0.0f; }

#pragma unroll 4
    for (int il = 0; il < CI; il++) {
        float4 p = ps[il * JT + lane];                                     // conflict-free LDS.128
        float4 v = *reinterpret_cast<const float4*>(vs + il * VST + bl0);  // broadcast LDS.128
        float g;
        g = satfma(v.x, p.x, p.y); r[0] = fmaf(g, p.z, r[0]); wv[0] = fmaf(g, p.w, wv[0]);
        g = satfma(v.y, p.x, p.y); r[1] = fmaf(g, p.z, r[1]); wv[1] = fmaf(g, p.w, wv[1]);
        g = satfma(v.z, p.x, p.y); r[2] = fmaf(g, p.z, r[2]); wv[2] = fmaf(g, p.w, wv[2]);
        g = satfma(v.w, p.x, p.y); r[3] = fmaf(g, p.z, r[3]); wv[3] = fmaf(g, p.w, wv[3]);
    }

    // plain coalesced partial stores (no atomics)
    float2* __restrict__ part = sensory ? g_spart : g_part;
#pragma unroll
    for (int k = 0; k < 4; k++) {
        int b = bg * BB + bl0 + k;
        part[((size_t)kc * Bn + b) * Nn + jg] = make_float2(r[k], wv[k]);
    }

    __threadfence();
    __syncthreads();
    __shared__ int lastFlag;
    const unsigned arrivals = FIRST ? 2u * KC : (unsigned)KC;
    if (tid == 0)
        lastFlag = (atomicAdd(&g_cnt[jt * NBG + bg], 1u) == arrivals - 1u);
    __syncthreads();
    if (!lastFlag) return;
    __threadfence();

    // ---- combine + v-update (only the last CTA for this (jt,bg)) ----
    int jo = jc0 + (tid & 31);
    float tj = tau[jo];
    int mo = jo - (Nn - Mn);
    float owj = 0.0f, obj = 0.0f;
    if (LAST && mo >= 0 && ow != nullptr) { owj = ow[mo]; obj = ob[mo]; }
#pragma unroll
    for (int k = 0; k < 4; k++) {
        int b = bg * BB + (tid >> 5) + k * 8;
        size_t base = (size_t)b * Nn + jo;
        float sr, sw;
        if (FIRST) {
            float sx = 0.0f, sy = 0.0f;
#pragma unroll
            for (int q = 0; q < KC; q++) {
                float2 p = g_spart[(size_t)q * (Bn * Nn) + base];
                sx += p.x; sy += p.y;
            }
            sr = sx + bias[jo];
            sw = sy;
            g_srev[base] = sr;
            g_sw[base]   = sw;
        } else {
            sr = g_srev[base];
            sw = g_sw[base];
        }
        float ax = 0.0f, ay = 0.0f;
#pragma unroll
        for (int q = 0; q < KC; q++) {
            float2 p = g_part[(size_t)q * (Bn * Nn) + base];
            ax += p.x; ay += p.y;
        }
        float SR = ax + sr;
        float SW = ay + sw;
        float v  = vin[base];
        float vn = (tj * v + DELTA * SR) / (tj + DELTA + DELTA * SW);
        vout[base] = vn;
        if (LAST && outp != nullptr && mo >= 0)
            outp[b * Mn + mo] = fmaf(vn, owj, obj);
    }
    if (tid == 0) g_cnt[jt * NBG + bg] = 0u;   // re-arm for next step kernel
}

// ---------------- host ----------------
extern "C" void kernel_launch(void* const* d_in, const int* in_sizes, int n_in,
                              void* d_out, int out_size)
{
    const float* inputs = (const float*)d_in[0];
    const float* states = (const float*)d_in[1];
    const float* tau    = (const float*)d_in[2];
    const float* bias   = (const float*)d_in[3];
    const float* erev   = (const float*)d_in[4];
    const float* wmat   = (const float*)d_in[5];
    const float* sigma  = (const float*)d_in[6];
    const float* mu     = (const float*)d_in[7];
    const float* serev  = (const float*)d_in[8];
    const float* swmat  = (const float*)d_in[9];
    const float* ssigma = (const float*)d_in[10];
    const float* smu    = (const float*)d_in[11];
    const float* mask   = (const float*)d_in[12];
    const float* smask  = (const float*)d_in[13];
    const float* iw     = (const float*)d_in[14];
    const float* ib     = (const float*)d_in[15];
    const float* ow     = (const float*)d_in[16];
    const float* ob     = (const float*)d_in[17];
    float* outF = (float*)d_out;

    float* vbuf = nullptr;
    cudaGetSymbolAddress((void**)&vbuf, g_v);

    prep_kernel<<<256, TPB>>>(sigma, mu, erev, wmat, mask,
                              ssigma, smu, serev, swmat, smask,
                              inputs, iw, ib);

    const float* cur = states;
    for (int u = 0; u < NUNF; u++) {
        bool first = (u == 0);
        bool last  = (u == NUNF - 1);
        float* nxt = vbuf + (u & 1) * (Bn * Nn);
        float* outp = nullptr;
        if (last) {
            // output is tuple (out[B,M], v[B,N]) flattened in order
            if (out_size >= Bn * Mn + Bn * Nn) { nxt = outF + Bn * Mn; outp = outF; }
            else if (out_size == Bn * Nn)      { nxt = outF; }
            else if (out_size >= Bn * Mn)      { outp = outF; }
        }
        dim3 grid(NJT, NBG, first ? 2 * KC : KC);
        if (first)
            step_kernel<true,  false><<<grid, TPB>>>(cur, nxt, tau, bias, nullptr, ow, ob);
        else if (last)
            step_kernel<false, true ><<<grid, TPB>>>(cur, nxt, tau, bias, outp, ow, ob);
        else
            step_kernel<false, false><<<grid, TPB>>>(cur, nxt, tau, bias, nullptr, ow, ob);
        cur = nxt;
    }
}

// round 8
// speedup vs baseline: 1.0196x; 1.0196x over previous
#include <cuda_runtime.h>

// SNSCell: B=64 batch, S=512 sensory, N=512 state, M=128 motor, 6 unfolds, dt=0.1
#define Bn 64
#define Nn 512
#define Sn 512
#define Mn 128
#define NUNF 6
#define DELTA (0.1f / 6.0f)

#define JT 32          // j (postsynaptic) tile per CTA (lane = j)
#define NJT 16         // Nn / JT
#define KC 16          // i-reduction splits
#define CI 32          // i chunk per CTA (Nn / KC)
#define NBG 4          // batch groups
#define BB 16          // batches per CTA
#define TPB 256        // 8 warps; warp -> 2 batches
#define VST 20         // padded smem stride for v chunk rows (floats)

// ---------------- scratch (static device memory; no allocations) ----------------
__device__ float4 g_P[Nn * Nn];       // fused internal params {1/2s, (s-mu)/2s, mask*erev, mask*w}
__device__ float4 g_SP[Sn * Nn];      // fused sensory params
__device__ float  g_x[Bn * Sn];       // mapped inputs
__device__ float  g_v[2 * Bn * Nn];   // ping-pong state
__device__ float  g_srev[Bn * Nn];    // sensory rev sum (+bias)
__device__ float  g_sw[Bn * Nn];      // sensory w sum
__device__ float2 g_part[KC * Bn * Nn];   // per-split partials {rev, w} (plain stores)
__device__ float2 g_spart[KC * Bn * Nn];  // sensory partials (first step only)
__device__ unsigned g_cnt[NJT * NBG];     // arrival counters (kept zeroed)

__device__ __forceinline__ float satfma(float a, float b, float c) {
    float d;
    asm("fma.rn.sat.f32 %0, %1, %2, %3;" : "=f"(d) : "f"(a), "f"(b), "f"(c));
    return d;
}

// ---------------- prep ----------------
__device__ __forceinline__ float4 fuse1(float sg, float m, float e, float wv, float mk) {
    float a = 1.0f / (2.0f * sg);
    float4 p;
    p.x = a;
    p.y = (sg - m) * a;
    p.z = mk * e;
    p.w = mk * wv;
    return p;
}

__global__ void prep_kernel(const float* __restrict__ sigma, const float* __restrict__ mu,
                            const float* __restrict__ erev,  const float* __restrict__ wmat,
                            const float* __restrict__ mask,
                            const float* __restrict__ ssigma, const float* __restrict__ smu,
                            const float* __restrict__ serev,  const float* __restrict__ swmat,
                            const float* __restrict__ smask,
                            const float* __restrict__ inputs, const float* __restrict__ iw,
                            const float* __restrict__ ib)
{
    int stride = gridDim.x * blockDim.x;
    int tid = blockIdx.x * blockDim.x + threadIdx.x;

    const float4* sg4 = (const float4*)sigma;
    const float4* mu4 = (const float4*)mu;
    const float4* er4 = (const float4*)erev;
    const float4* w4  = (const float4*)wmat;
    const float4* mk4 = (const float4*)mask;
    for (int i = tid; i < Nn * Nn / 4; i += stride) {
        float4 sg = sg4[i], m = mu4[i], e = er4[i], ww = w4[i], mk = mk4[i];
        g_P[4*i+0] = fuse1(sg.x, m.x, e.x, ww.x, mk.x);
        g_P[4*i+1] = fuse1(sg.y, m.y, e.y, ww.y, mk.y);
        g_P[4*i+2] = fuse1(sg.z, m.z, e.z, ww.z, mk.z);
        g_P[4*i+3] = fuse1(sg.w, m.w, e.w, ww.w, mk.w);
    }
    const float4* ssg4 = (const float4*)ssigma;
    const float4* smu4 = (const float4*)smu;
    const float4* ser4 = (const float4*)serev;
    const float4* sw4  = (const float4*)swmat;
    const float4* smk4 = (const float4*)smask;
    for (int i = tid; i < Sn * Nn / 4; i += stride) {
        float4 sg = ssg4[i], m = smu4[i], e = ser4[i], ww = sw4[i], mk = smk4[i];
        g_SP[4*i+0] = fuse1(sg.x, m.x, e.x, ww.x, mk.x);
        g_SP[4*i+1] = fuse1(sg.y, m.y, e.y, ww.y, mk.y);
        g_SP[4*i+2] = fuse1(sg.z, m.z, e.z, ww.z, mk.z);
        g_SP[4*i+3] = fuse1(sg.w, m.w, e.w, ww.w, mk.w);
    }
    const float4* in4 = (const float4*)inputs;
    const float4* iw4 = (const float4*)iw;
    const float4* ib4 = (const float4*)ib;
    float4* x4 = (float4*)g_x;
    for (int i = tid; i < Bn * Sn / 4; i += stride) {
        int s4i = i & (Sn / 4 - 1);
        float4 a = in4[i], wv = iw4[s4i], bv = ib4[s4i];
        float4 o;
        o.x = fmaf(a.x, wv.x, bv.x);
        o.y = fmaf(a.y, wv.y, bv.y);
        o.z = fmaf(a.z, wv.z, bv.z);
        o.w = fmaf(a.w, wv.w, bv.w);
        x4[i] = o;
    }
    if (tid < NJT * NBG) g_cnt[tid] = 0u;
}

// ---------------- fused reduce + combine step kernel ----------------
// CTA = (jt, bg, z). FIRST: z in [0,32): z<16 -> internal chunk z on vin,
// z>=16 -> sensory chunk (z-16) on g_x into g_spart. Otherwise z in [0,16).
// Each CTA: 32 i x 32 j x 16 b. Warp -> 2 batches, lane -> j. Partials are plain
// float2 stores; the last CTA for (jt,bg) combines all planes + v-update.
template <bool FIRST, bool LAST>
__global__ void __launch_bounds__(TPB) step_kernel(const float* __restrict__ vin,
                                                   float* __restrict__ vout,
                                                   const float* __restrict__ tau,
                                                   const float* __restrict__ bias,
                                                   float* __restrict__ outp,
                                                   const float* __restrict__ ow,
                                                   const float* __restrict__ ob)
{
    __shared__ __align__(16) float  vs[CI * VST];
    __shared__ __align__(16) float4 ps[CI * JT];

    int jt = blockIdx.x, bg = blockIdx.y, z = blockIdx.z;
    bool sensory = FIRST && (z >= KC);
    int kc = sensory ? z - KC : z;
    const float4* __restrict__ P   = sensory ? g_SP : g_P;
    const float*  __restrict__ src = sensory ? g_x  : vin;

    int tid = threadIdx.x;
    int i0  = kc * CI;
    int jc0 = jt * JT;

    // stage v/x chunk transposed: vs[il][b]; lanes sweep il -> coalesced
    for (int t = tid; t < CI * BB; t += TPB) {
        int il = t & (CI - 1);
        int b  = t >> 5;
        vs[il * VST + b] = src[(bg * BB + b) * 512 + i0 + il];
    }
    // stage P tile: ps[row*32 + col]; 512B-contiguous reads per warp
    for (int t = tid; t < CI * JT; t += TPB) {
        int row = t >> 5;
        int col = t & 31;
        ps[t] = __ldg(&P[(size_t)(i0 + row) * Nn + jc0 + col]);
    }
    __syncthreads();

    int lane = tid & 31;
    int warp = tid >> 5;
    int bl0  = warp * 2;          // local batch base (0..14)
    int jg   = jc0 + lane;

    float r0 = 0.f, w0 = 0.f, r1 = 0.f, w1 = 0.f;

#pragma unroll 8
    for (int il = 0; il < CI; il++) {
        float4 p = ps[il * JT + lane];                                       // conflict-free LDS.128
        float2 v = *reinterpret_cast<const float2*>(vs + il * VST + bl0);    // broadcast LDS.64
        float g0 = satfma(v.x, p.x, p.y);
        float g1 = satfma(v.y, p.x, p.y);
        r0 = fmaf(g0, p.z, r0); w0 = fmaf(g0, p.w, w0);
        r1 = fmaf(g1, p.z, r1); w1 = fmaf(g1, p.w, w1);
    }

    // plain coalesced partial stores (no atomics)
    float2* __restrict__ part = sensory ? g_spart : g_part;
    {
        int b = bg * BB + bl0;
        part[((size_t)kc * Bn + b) * Nn + jg]     = make_float2(r0, w0);
        part[((size_t)kc * Bn + b + 1) * Nn + jg] = make_float2(r1, w1);
    }

    __threadfence();
    __syncthreads();
    __shared__ int lastFlag;
    const unsigned arrivals = FIRST ? 2u * KC : (unsigned)KC;
    if (tid == 0)
        lastFlag = (atomicAdd(&g_cnt[jt * NBG + bg], 1u) == arrivals - 1u);
    __syncthreads();
    if (!lastFlag) return;
    __threadfence();

    // ---- combine + v-update (only last CTA for this (jt,bg)) ----
    int jo = jc0 + lane;
    float tj = tau[jo];
    int mo = jo - (Nn - Mn);
    float owj = 0.0f, obj = 0.0f;
    if (LAST && mo >= 0 && ow != nullptr) { owj = ow[mo]; obj = ob[mo]; }
#pragma unroll
    for (int k = 0; k < 2; k++) {
        int b = bg * BB + bl0 + k;
        size_t base = (size_t)b * Nn + jo;
        float sr, sw;
        if (FIRST) {
            float sx = 0.0f, sy = 0.0f;
#pragma unroll
            for (int q = 0; q < KC; q++) {
                float2 p = g_spart[(size_t)q * (Bn * Nn) + base];
                sx += p.x; sy += p.y;
            }
            sr = sx + bias[jo];
            sw = sy;
            g_srev[base] = sr;
            g_sw[base]   = sw;
        } else {
            sr = g_srev[base];
            sw = g_sw[base];
        }
        float ax = 0.0f, ay = 0.0f;
#pragma unroll
        for (int q = 0; q < KC; q++) {
            float2 p = g_part[(size_t)q * (Bn * Nn) + base];
            ax += p.x; ay += p.y;
        }
        float SR = ax + sr;
        float SW = ay + sw;
        float v  = vin[base];
        float vn = (tj * v + DELTA * SR) / (tj + DELTA + DELTA * SW);
        vout[base] = vn;
        if (LAST && outp != nullptr && mo >= 0)
            outp[b * Mn + mo] = fmaf(vn, owj, obj);
    }
    if (tid == 0) g_cnt[jt * NBG + bg] = 0u;   // re-arm for next step
}

// ---------------- host ----------------
extern "C" void kernel_launch(void* const* d_in, const int* in_sizes, int n_in,
                              void* d_out, int out_size)
{
    const float* inputs = (const float*)d_in[0];
    const float* states = (const float*)d_in[1];
    const float* tau    = (const float*)d_in[2];
    const float* bias   = (const float*)d_in[3];
    const float* erev   = (const float*)d_in[4];
    const float* wmat   = (const float*)d_in[5];
    const float* sigma  = (const float*)d_in[6];
    const float* mu     = (const float*)d_in[7];
    const float* serev  = (const float*)d_in[8];
    const float* swmat  = (const float*)d_in[9];
    const float* ssigma = (const float*)d_in[10];
    const float* smu    = (const float*)d_in[11];
    const float* mask   = (const float*)d_in[12];
    const float* smask  = (const float*)d_in[13];
    const float* iw     = (const float*)d_in[14];
    const float* ib     = (const float*)d_in[15];
    const float* ow     = (const float*)d_in[16];
    const float* ob     = (const float*)d_in[17];
    float* outF = (float*)d_out;

    float* vbuf = nullptr;
    cudaGetSymbolAddress((void**)&vbuf, g_v);

    prep_kernel<<<256, TPB>>>(sigma, mu, erev, wmat, mask,
                              ssigma, smu, serev, swmat, smask,
                              inputs, iw, ib);

    const float* cur = states;
    for (int u = 0; u < NUNF; u++) {
        bool first = (u == 0);
        bool last  = (u == NUNF - 1);
        float* nxt = vbuf + (u & 1) * (Bn * Nn);
        float* outp = nullptr;
        if (last) {
            // output is tuple (out[B,M], v[B,N]) flattened in order
            if (out_size >= Bn * Mn + Bn * Nn) { nxt = outF + Bn * Mn; outp = outF; }
            else if (out_size == Bn * Nn)      { nxt = outF; }
            else if (out_size >= Bn * Mn)      { outp = outF; }
        }
        dim3 grid(NJT, NBG, first ? 2 * KC : KC);
        if (first)
            step_kernel<true,  false><<<grid, TPB>>>(cur, nxt, tau, bias, nullptr, ow, ob);
        else if (last)
            step_kernel<false, true ><<<grid, TPB>>>(cur, nxt, tau, bias, outp, ow, ob);
        else
            step_kernel<false, false><<<grid, TPB>>>(cur, nxt, tau, bias, nullptr, ow, ob);
        cur = nxt;
    }
}